// round 15
// baseline (speedup 1.0000x reference)
#include <cuda_runtime.h>
#include <cuda_fp16.h>
#include <cstdint>
#include <cstddef>

#define E_TOTAL 400000
#define DIM 128
#define G_TOTAL 512
#define BM 128
#define NTHREADS 256
#define SSTR 136                         // halves; 272B rows -> conflict-free ldmatrix
#define CHUNK_HALVES (DIM * SSTR)        // 17408 halves = 34816 B per image
#define IMG_BYTES (CHUNK_HALVES * 2)     // 34816 B
#define SMEM_BYTES (2 * IMG_BYTES)       // sA + sB = 69632 B

// Scratch (static device arrays allowed; allocation is not)
__device__ float  g_UB[G_TOTAL * DIM];                    // u @ W1[384:512] + b1 (fp32 exact)
__device__ __align__(16) __half g_W[4 * CHUNK_HALVES];    // fp16 weights, [chunk][n][k] stride 136
__device__ int    g_batch[E_TOTAL];

__device__ __forceinline__ void cp_async16(uint32_t dst_smem, const void* src) {
    asm volatile("cp.async.cg.shared.global [%0], [%1], 16;\n" :: "r"(dst_smem), "l"(src));
}
__device__ __forceinline__ void cp_async_commit() {
    asm volatile("cp.async.commit_group;\n" ::: "memory");
}
__device__ __forceinline__ void cp_async_wait0() {
    asm volatile("cp.async.wait_group 0;\n" ::: "memory");
}
__device__ __forceinline__ void ldsm4(unsigned& r0, unsigned& r1, unsigned& r2, unsigned& r3,
                                      uint32_t addr) {
    asm volatile("ldmatrix.sync.aligned.m8n8.x4.shared.b16 {%0,%1,%2,%3}, [%4];"
                 : "=r"(r0), "=r"(r1), "=r"(r2), "=r"(r3) : "r"(addr));
}
__device__ __forceinline__ void mma16816(float* c, const unsigned* a, unsigned b0, unsigned b1) {
    asm volatile(
        "mma.sync.aligned.m16n8k16.row.col.f32.f16.f16.f32 "
        "{%0,%1,%2,%3},{%4,%5,%6,%7},{%8,%9},{%0,%1,%2,%3};\n"
        : "+f"(c[0]), "+f"(c[1]), "+f"(c[2]), "+f"(c[3])
        : "r"(a[0]), "r"(a[1]), "r"(a[2]), "r"(a[3]), "r"(b0), "r"(b1));
}

// ---------------------------------------------------------------------------
// batch may arrive as int32 (JAX x64 disabled) or int64 (see R1 notes).
// ---------------------------------------------------------------------------
__global__ void batch_norm_kernel(const int* __restrict__ bp32) {
    bool is64 = (bp32[E_TOTAL - 1] == 0);
    int i = blockIdx.x * blockDim.x + threadIdx.x;
    if (i < E_TOTAL)
        g_batch[i] = is64 ? (int)(((const long long*)bp32)[i]) : bp32[i];
}

// UB[g][n] = b1[n] + sum_k u[g][k] * W1[384+k][n]   (exact fp32, tiny)
__global__ void ub_kernel(const float* __restrict__ u, const float* __restrict__ W1,
                          const float* __restrict__ b1) {
    __shared__ float us[DIM];
    int gi = blockIdx.x, n = threadIdx.x;
    us[n] = u[gi * DIM + n];
    __syncthreads();
    float acc = b1[n];
    const float* w = W1 + 3 * DIM * DIM + n;
#pragma unroll 8
    for (int k = 0; k < DIM; ++k) acc += us[k] * w[k * DIM];
    g_UB[gi * DIM + n] = acc;
}

// One-time weight transform: chunk c<3 -> W1 K-rows [c*128,c*128+128); c=3 -> W2.
// Image [n][k] halves, stride 136 (pads stay 0 in bss).
__global__ void wconv_kernel(const float* __restrict__ W1, const float* __restrict__ W2) {
    int c = blockIdx.x, n = blockIdx.y, k = threadIdx.x;
    float v = (c < 3) ? W1[(c * DIM + k) * DIM + n] : W2[k * DIM + n];
    g_W[c * CHUNK_HALVES + n * SSTR + k] = __float2half_rn(v);
}

// ---- fragment load for one k16 step: 4 A frags (m16) + 4 B frags (n8) ----
__device__ __forceinline__ void load_frags(unsigned a[4][4], unsigned b[4][2],
                                           const uint32_t aB[4], const uint32_t bB[2],
                                           uint32_t ko) {
#pragma unroll
    for (int mi = 0; mi < 4; ++mi)
        ldsm4(a[mi][0], a[mi][1], a[mi][2], a[mi][3], aB[mi] + ko);
#pragma unroll
    for (int p = 0; p < 2; ++p) {
        unsigned r0, r1, r2, r3;
        ldsm4(r0, r1, r2, r3, bB[p] + ko);
        b[2 * p][0] = r0; b[2 * p][1] = r1;
        b[2 * p + 1][0] = r2; b[2 * p + 1][1] = r3;
    }
}

// 8 k16-steps over a K=128 chunk, fragment double-buffered: k-step ks+1's
// LDSMs issue before ks's 16 MMAs, so LDSM latency hides under HMMA issue.
__device__ __forceinline__ void mma_block(const uint32_t aB[4], const uint32_t bB[2],
                                          float acc[4][4][4]) {
    unsigned a[2][4][4], b[2][4][2];
    load_frags(a[0], b[0], aB, bB, 0);
#pragma unroll
    for (int ks = 0; ks < 8; ++ks) {
        const int cur = ks & 1, nxt = cur ^ 1;
        if (ks < 7) load_frags(a[nxt], b[nxt], aB, bB, (uint32_t)(ks + 1) * 32);
#pragma unroll
        for (int mi = 0; mi < 4; ++mi)
#pragma unroll
            for (int ni = 0; ni < 4; ++ni)
                mma16816(acc[mi][ni], a[cur][mi], b[cur][ni][0], b[cur][ni][1]);
    }
}

// Load one 128x128 fp32 chunk into registers (16 float4 / thread).
__device__ __forceinline__ void ldg_chunk(const float* __restrict__ Ap, int e0, int tid,
                                          float4 pf[16]) {
#pragma unroll
    for (int it = 0; it < 16; ++it) {
        int i = it * NTHREADS + tid;
        int row = i >> 5, c4 = (i & 31) << 2;
        pf[it] = *reinterpret_cast<const float4*>(Ap + (size_t)(e0 + row) * DIM + c4);
    }
}

// Convert to fp16 + store into sA. Warp writes within one row -> conflict-free.
__device__ __forceinline__ void sts_chunk(__half* __restrict__ sA, int tid,
                                          const float4 pf[16]) {
#pragma unroll
    for (int it = 0; it < 16; ++it) {
        int i = it * NTHREADS + tid;
        int row = i >> 5, c4 = (i & 31) << 2;
        __half2 h0 = __floats2half2_rn(pf[it].x, pf[it].y);
        __half2 h1 = __floats2half2_rn(pf[it].z, pf[it].w);
        *reinterpret_cast<__half2*>(sA + row * SSTR + c4) = h0;
        *reinterpret_cast<__half2*>(sA + row * SSTR + c4 + 2) = h1;
    }
}

__global__ __launch_bounds__(NTHREADS, 1)
void edge_mlp_kernel(const float* __restrict__ src, const float* __restrict__ dst,
                     const float* __restrict__ edge,
                     const float* __restrict__ b2, float* __restrict__ out) {
    extern __shared__ __half smem_h[];
    __half* sA = smem_h;                  // [128][136] halves: A chunk / H
    __half* sB = smem_h + CHUNK_HALVES;   // [128][136] halves: weight chunk [n][k]
    const uint32_t sA_u32 = (uint32_t)__cvta_generic_to_shared(sA);
    const uint32_t sB_u32 = (uint32_t)__cvta_generic_to_shared(sB);

    const int tid = threadIdx.x;
    const int warp = tid >> 5, lane = tid & 31;
    const int wn = warp & 3, wm = warp >> 2;      // 2 x 4 warp grid, 64x32 tiles
    const int g = lane >> 2, tg = lane & 3;
    const int e0 = blockIdx.x * BM;

    // per-lane ldmatrix base addresses (bytes, shared space)
    const int q = lane >> 3, rr = lane & 7;
    uint32_t aB[4], bB[2];
#pragma unroll
    for (int mi = 0; mi < 4; ++mi) {
        int row = wm * 64 + mi * 16 + rr + (q & 1) * 8;
        int kof = (q >> 1) * 8;
        aB[mi] = sA_u32 + (row * SSTR + kof) * 2;
    }
#pragma unroll
    for (int p = 0; p < 2; ++p) {
        int n = wn * 32 + p * 16 + rr + (q >> 1) * 8;
        int kof = (q & 1) * 8;
        bB[p] = sB_u32 + (n * SSTR + kof) * 2;
    }

    float acc[4][4][4];
#pragma unroll
    for (int mi = 0; mi < 4; ++mi)
#pragma unroll
        for (int ni = 0; ni < 4; ++ni)
#pragma unroll
            for (int j = 0; j < 4; ++j) acc[mi][ni][j] = 0.f;

    const float* parts[3] = {src, dst, edge};
    float4 pf[16];
    ldg_chunk(parts[0], e0, tid, pf);          // prefetch chunk 0

    // ---------------- layer 1: three K=128 chunks ----------------
#pragma unroll 1
    for (int part = 0; part < 3; ++part) {
        __syncthreads();                       // prior sA/sB readers done
        // weight chunk -> sB via linear cp.async (pre-converted fp16, conflict-free)
        {
            const char* wsrc = (const char*)(g_W + (size_t)part * CHUNK_HALVES);
#pragma unroll
            for (int it = 0; it < 9; ++it) {
                int i = it * NTHREADS + tid;   // 16B unit
                if (i < IMG_BYTES / 16)
                    cp_async16(sB_u32 + i * 16, wsrc + (size_t)i * 16);
            }
            cp_async_commit();
        }
        sts_chunk(sA, tid, pf);                // convert + store current A chunk
        if (part < 2) ldg_chunk(parts[part + 1], e0, tid, pf);   // overlap next LDGs
        cp_async_wait0();
        __syncthreads();
        mma_block(aB, bB, acc);
    }

    __syncthreads();                           // all warps done reading sA/sB

    // kick W2 staging early; overlaps epilogue 1
    {
        const char* wsrc = (const char*)(g_W + (size_t)3 * CHUNK_HALVES);
#pragma unroll
        for (int it = 0; it < 9; ++it) {
            int i = it * NTHREADS + tid;
            if (i < IMG_BYTES / 16)
                cp_async16(sB_u32 + i * 16, wsrc + (size_t)i * 16);
        }
        cp_async_commit();
    }

    // ------ epilogue 1: + UB[batch] gather, relu, H -> sA (fp16) ------
#pragma unroll
    for (int mi = 0; mi < 4; ++mi) {
        const int rA = wm * 64 + mi * 16 + g;
        const int rB = rA + 8;
        const int ga = g_batch[e0 + rA];
        const int gb = g_batch[e0 + rB];
#pragma unroll
        for (int ni = 0; ni < 4; ++ni) {
            const int c = wn * 32 + ni * 8 + tg * 2;
            float2 ua = *reinterpret_cast<const float2*>(g_UB + (size_t)ga * DIM + c);
            float2 ub = *reinterpret_cast<const float2*>(g_UB + (size_t)gb * DIM + c);
            float h0 = fmaxf(acc[mi][ni][0] + ua.x, 0.f);
            float h1 = fmaxf(acc[mi][ni][1] + ua.y, 0.f);
            float h2 = fmaxf(acc[mi][ni][2] + ub.x, 0.f);
            float h3 = fmaxf(acc[mi][ni][3] + ub.y, 0.f);
            *reinterpret_cast<__half2*>(sA + rA * SSTR + c) = __floats2half2_rn(h0, h1);
            *reinterpret_cast<__half2*>(sA + rB * SSTR + c) = __floats2half2_rn(h2, h3);
        }
    }

    // reset accumulators for layer 2
#pragma unroll
    for (int mi = 0; mi < 4; ++mi)
#pragma unroll
        for (int ni = 0; ni < 4; ++ni)
#pragma unroll
            for (int j = 0; j < 4; ++j) acc[mi][ni][j] = 0.f;

    cp_async_wait0();
    __syncthreads();

    // ---------------- layer 2: out = H @ W2 ----------------
    mma_block(aB, bB, acc);

    // ---------------- epilogue 2: + b2, fp32 store ----------------
#pragma unroll
    for (int mi = 0; mi < 4; ++mi) {
        const int rA = wm * 64 + mi * 16 + g;
        const int rB = rA + 8;
#pragma unroll
        for (int ni = 0; ni < 4; ++ni) {
            const int c = wn * 32 + ni * 8 + tg * 2;
            float2 bv = *reinterpret_cast<const float2*>(b2 + c);
            *reinterpret_cast<float2*>(out + (size_t)(e0 + rA) * DIM + c) =
                make_float2(acc[mi][ni][0] + bv.x, acc[mi][ni][1] + bv.y);
            *reinterpret_cast<float2*>(out + (size_t)(e0 + rB) * DIM + c) =
                make_float2(acc[mi][ni][2] + bv.x, acc[mi][ni][3] + bv.y);
        }
    }
}

extern "C" void kernel_launch(void* const* d_in, const int* in_sizes, int n_in,
                              void* d_out, int out_size) {
    const float* src  = (const float*)d_in[0];
    const float* dst  = (const float*)d_in[1];
    const float* edge = (const float*)d_in[2];
    const float* u    = (const float*)d_in[3];
    const int*   bat  = (const int*)d_in[4];
    const float* W1   = (const float*)d_in[5];
    const float* b1   = (const float*)d_in[6];
    const float* W2   = (const float*)d_in[7];
    const float* b2   = (const float*)d_in[8];
    float* out = (float*)d_out;
    (void)in_sizes; (void)n_in; (void)out_size;

    cudaFuncSetAttribute(edge_mlp_kernel,
                         cudaFuncAttributeMaxDynamicSharedMemorySize, SMEM_BYTES);

    batch_norm_kernel<<<(E_TOTAL + 255) / 256, 256>>>(bat);
    ub_kernel<<<G_TOTAL, DIM>>>(u, W1, b1);
    wconv_kernel<<<dim3(4, DIM), DIM>>>(W1, W2);
    edge_mlp_kernel<<<E_TOTAL / BM, NTHREADS, SMEM_BYTES>>>(src, dst, edge, b2, out);
}

// round 17
// speedup vs baseline: 1.2623x; 1.2623x over previous
#include <cuda_runtime.h>
#include <cuda_fp16.h>
#include <cstdint>
#include <cstddef>

#define E_TOTAL 400000
#define DIM 128
#define G_TOTAL 512
#define BM 128
#define NTHREADS 256
#define SSTR 136                         // halves; 272B rows -> conflict-free ldmatrix
#define CHUNK_HALVES (DIM * SSTR)        // 17408 halves = 34816 B per image
#define IMG_BYTES (CHUNK_HALVES * 2)     // 34816 B
#define SMEM_BYTES (2 * IMG_BYTES)       // sA + sB = 69632 B

// merged prep-kernel block ranges
#define PREP_BATCH_BLKS ((E_TOTAL + 255) / 256)          // 1563
#define PREP_UB_BLKS    (G_TOTAL / 2)                    // 256 (2 groups / block)
#define PREP_W_BLKS     ((4 * DIM * DIM) / 256)          // 256
#define PREP_BLKS       (PREP_BATCH_BLKS + PREP_UB_BLKS + PREP_W_BLKS)

// Scratch (static device arrays allowed; allocation is not)
__device__ float  g_UB[G_TOTAL * DIM];                    // u @ W1[384:512] + b1 (fp32 exact)
__device__ __align__(16) __half g_W[4 * CHUNK_HALVES];    // fp16 weights, [chunk][n][k] stride 136
__device__ int    g_batch[E_TOTAL];

__device__ __forceinline__ void cp_async16(uint32_t dst_smem, const void* src) {
    asm volatile("cp.async.cg.shared.global [%0], [%1], 16;\n" :: "r"(dst_smem), "l"(src));
}
__device__ __forceinline__ void cp_async_commit() {
    asm volatile("cp.async.commit_group;\n" ::: "memory");
}
__device__ __forceinline__ void cp_async_wait0() {
    asm volatile("cp.async.wait_group 0;\n" ::: "memory");
}
__device__ __forceinline__ void ldsm4(unsigned& r0, unsigned& r1, unsigned& r2, unsigned& r3,
                                      uint32_t addr) {
    asm volatile("ldmatrix.sync.aligned.m8n8.x4.shared.b16 {%0,%1,%2,%3}, [%4];"
                 : "=r"(r0), "=r"(r1), "=r"(r2), "=r"(r3) : "r"(addr));
}
__device__ __forceinline__ void mma16816(float* c, const unsigned* a, unsigned b0, unsigned b1) {
    asm volatile(
        "mma.sync.aligned.m16n8k16.row.col.f32.f16.f16.f32 "
        "{%0,%1,%2,%3},{%4,%5,%6,%7},{%8,%9},{%0,%1,%2,%3};\n"
        : "+f"(c[0]), "+f"(c[1]), "+f"(c[2]), "+f"(c[3])
        : "r"(a[0]), "r"(a[1]), "r"(a[2]), "r"(a[3]), "r"(b0), "r"(b1));
}

// ---------------------------------------------------------------------------
// Merged one-shot prep kernel. Block ranges:
//   [0, 1563)          : batch normalize (int32-or-int64 -> g_batch)
//   [1563, 1563+256)   : g_UB = u @ W1[384:512] + b1 (2 groups per block)
//   [1819, 1819+256)   : weight transform -> fp16 [chunk][n][k] stride-136 images
// batch dtype detect: sorted over 400k draws from [0,512); if int64, high word
// of last element is 0; if int32, it's the last (largest) element, nonzero w.h.p.
// ---------------------------------------------------------------------------
__global__ void prep_kernel(const int* __restrict__ bp32, const float* __restrict__ u,
                            const float* __restrict__ W1, const float* __restrict__ b1,
                            const float* __restrict__ W2) {
    const int blk = blockIdx.x, tid = threadIdx.x;
    if (blk < PREP_BATCH_BLKS) {
        bool is64 = (bp32[E_TOTAL - 1] == 0);
        int i = blk * 256 + tid;
        if (i < E_TOTAL)
            g_batch[i] = is64 ? (int)(((const long long*)bp32)[i]) : bp32[i];
    } else if (blk < PREP_BATCH_BLKS + PREP_UB_BLKS) {
        __shared__ float us[2][DIM];
        int gi = (blk - PREP_BATCH_BLKS) * 2 + (tid >> 7);
        int n = tid & (DIM - 1);
        us[tid >> 7][n] = u[gi * DIM + n];
        __syncthreads();
        float acc = b1[n];
        const float* w = W1 + 3 * DIM * DIM + n;
        const float* uu = us[tid >> 7];
#pragma unroll 8
        for (int k = 0; k < DIM; ++k) acc += uu[k] * w[k * DIM];
        g_UB[gi * DIM + n] = acc;
    } else {
        int idx = (blk - PREP_BATCH_BLKS - PREP_UB_BLKS) * 256 + tid;  // < 65536
        int c = idx >> 14, rem = idx & 16383;
        int k = rem >> 7, n = rem & (DIM - 1);
        float v = (c < 3) ? W1[(c * DIM + k) * DIM + n] : W2[k * DIM + n];
        g_W[c * CHUNK_HALVES + n * SSTR + k] = __float2half_rn(v);
    }
}

// ---- fragment load for one k16 step (R9 geometry: m32 x n64 warp tile) ----
__device__ __forceinline__ void load_frags(unsigned a[2][4], unsigned b[4][4],
                                           const uint32_t aB[2], const uint32_t bB[4],
                                           uint32_t ko) {
    ldsm4(a[0][0], a[0][1], a[0][2], a[0][3], aB[0] + ko);
    ldsm4(a[1][0], a[1][1], a[1][2], a[1][3], aB[1] + ko);
#pragma unroll
    for (int p = 0; p < 4; ++p)
        ldsm4(b[p][0], b[p][1], b[p][2], b[p][3], bB[p] + ko);
}

// 8 k16-steps, fragment double-buffered: ks+1's LDSMs issue before ks's MMAs.
__device__ __forceinline__ void mma_block(const uint32_t aB[2], const uint32_t bB[4],
                                          float acc[2][8][4]) {
    unsigned a[2][2][4], b[2][4][4];
    load_frags(a[0], b[0], aB, bB, 0);
#pragma unroll
    for (int ks = 0; ks < 8; ++ks) {
        const int cur = ks & 1, nxt = cur ^ 1;
        if (ks < 7) load_frags(a[nxt], b[nxt], aB, bB, (uint32_t)(ks + 1) * 32);
#pragma unroll
        for (int p = 0; p < 4; ++p) {
            mma16816(acc[0][2 * p + 0], a[cur][0], b[cur][p][0], b[cur][p][1]);
            mma16816(acc[0][2 * p + 1], a[cur][0], b[cur][p][2], b[cur][p][3]);
            mma16816(acc[1][2 * p + 0], a[cur][1], b[cur][p][0], b[cur][p][1]);
            mma16816(acc[1][2 * p + 1], a[cur][1], b[cur][p][2], b[cur][p][3]);
        }
    }
}

// Load one 128x128 fp32 chunk and convert to packed fp16 (uint2 = 2 x half2).
__device__ __forceinline__ void ldg_cvt_chunk(const float* __restrict__ Ap, int e0, int tid,
                                              uint2 pf[16]) {
#pragma unroll
    for (int it = 0; it < 16; ++it) {
        int i = it * NTHREADS + tid;
        int row = i >> 5, c4 = (i & 31) << 2;
        float4 v = *reinterpret_cast<const float4*>(Ap + (size_t)(e0 + row) * DIM + c4);
        __half2 h0 = __floats2half2_rn(v.x, v.y);
        __half2 h1 = __floats2half2_rn(v.z, v.w);
        pf[it].x = *reinterpret_cast<unsigned*>(&h0);
        pf[it].y = *reinterpret_cast<unsigned*>(&h1);
    }
}

// Store packed fp16 chunk into sA (one 8B STS per element; conflict-free).
__device__ __forceinline__ void sts_chunk(__half* __restrict__ sA, int tid,
                                          const uint2 pf[16]) {
#pragma unroll
    for (int it = 0; it < 16; ++it) {
        int i = it * NTHREADS + tid;
        int row = i >> 5, c4 = (i & 31) << 2;
        *reinterpret_cast<uint2*>(sA + row * SSTR + c4) = pf[it];
    }
}

__global__ __launch_bounds__(NTHREADS, 1)
void edge_mlp_kernel(const float* __restrict__ src, const float* __restrict__ dst,
                     const float* __restrict__ edge,
                     const float* __restrict__ b2, float* __restrict__ out) {
    extern __shared__ __half smem_h[];
    __half* sA = smem_h;                  // [128][136] halves: A chunk / H
    __half* sB = smem_h + CHUNK_HALVES;   // [128][136] halves: weight chunk [n][k]
    const uint32_t sA_u32 = (uint32_t)__cvta_generic_to_shared(sA);
    const uint32_t sB_u32 = (uint32_t)__cvta_generic_to_shared(sB);

    const int tid = threadIdx.x;
    const int warp = tid >> 5, lane = tid & 31;
    const int wm = warp & 3, wn = warp >> 2;      // 4 x 2 grid, 32x64 tiles
    const int g = lane >> 2, tg = lane & 3;
    const int e0 = blockIdx.x * BM;

    // per-lane ldmatrix base addresses (bytes, shared space)
    const int q = lane >> 3, rr = lane & 7;
    uint32_t aB[2], bB[4];
#pragma unroll
    for (int mi = 0; mi < 2; ++mi) {
        int row = wm * 32 + mi * 16 + rr + (q & 1) * 8;
        int kof = (q >> 1) * 8;
        aB[mi] = sA_u32 + (row * SSTR + kof) * 2;
    }
#pragma unroll
    for (int p = 0; p < 4; ++p) {
        int n = wn * 64 + p * 16 + rr + (q >> 1) * 8;
        int kof = (q & 1) * 8;
        bB[p] = sB_u32 + (n * SSTR + kof) * 2;
    }

    float acc[2][8][4];
#pragma unroll
    for (int mi = 0; mi < 2; ++mi)
#pragma unroll
        for (int ni = 0; ni < 8; ++ni)
#pragma unroll
            for (int j = 0; j < 4; ++j) acc[mi][ni][j] = 0.f;

    const float* parts[3] = {src, dst, edge};
    uint2 pf[16];
    ldg_cvt_chunk(parts[0], e0, tid, pf);      // prefetch chunk 0 (fp16-packed)

    // ---------------- layer 1: three K=128 chunks ----------------
#pragma unroll 1
    for (int part = 0; part < 3; ++part) {
        __syncthreads();                       // prior sA/sB readers done
        // weight chunk -> sB via linear cp.async (pre-converted fp16, conflict-free)
        {
            const char* wsrc = (const char*)(g_W + (size_t)part * CHUNK_HALVES);
#pragma unroll
            for (int it = 0; it < 9; ++it) {
                int i = it * NTHREADS + tid;   // 16B unit
                if (i < IMG_BYTES / 16)
                    cp_async16(sB_u32 + i * 16, wsrc + (size_t)i * 16);
            }
            cp_async_commit();
        }
        sts_chunk(sA, tid, pf);                // store current A chunk (8B STS)
        if (part < 2) ldg_cvt_chunk(parts[part + 1], e0, tid, pf);  // overlap next
        cp_async_wait0();
        __syncthreads();
        mma_block(aB, bB, acc);
    }

    __syncthreads();                           // all warps done reading sA/sB

    // kick W2 staging early; overlaps epilogue 1
    {
        const char* wsrc = (const char*)(g_W + (size_t)3 * CHUNK_HALVES);
#pragma unroll
        for (int it = 0; it < 9; ++it) {
            int i = it * NTHREADS + tid;
            if (i < IMG_BYTES / 16)
                cp_async16(sB_u32 + i * 16, wsrc + (size_t)i * 16);
        }
        cp_async_commit();
    }

    // ------ epilogue 1: + UB[batch] gather, relu, H -> sA (fp16) ------
#pragma unroll
    for (int mi = 0; mi < 2; ++mi) {
        const int rA = wm * 32 + mi * 16 + g;
        const int rB = rA + 8;
        const int ga = g_batch[e0 + rA];
        const int gb = g_batch[e0 + rB];
#pragma unroll
        for (int ni = 0; ni < 8; ++ni) {
            const int c = wn * 64 + ni * 8 + tg * 2;
            float2 ua = *reinterpret_cast<const float2*>(g_UB + (size_t)ga * DIM + c);
            float2 ub = *reinterpret_cast<const float2*>(g_UB + (size_t)gb * DIM + c);
            float h0 = fmaxf(acc[mi][ni][0] + ua.x, 0.f);
            float h1 = fmaxf(acc[mi][ni][1] + ua.y, 0.f);
            float h2 = fmaxf(acc[mi][ni][2] + ub.x, 0.f);
            float h3 = fmaxf(acc[mi][ni][3] + ub.y, 0.f);
            *reinterpret_cast<__half2*>(sA + rA * SSTR + c) = __floats2half2_rn(h0, h1);
            *reinterpret_cast<__half2*>(sA + rB * SSTR + c) = __floats2half2_rn(h2, h3);
        }
    }

    // reset accumulators for layer 2
#pragma unroll
    for (int mi = 0; mi < 2; ++mi)
#pragma unroll
        for (int ni = 0; ni < 8; ++ni)
#pragma unroll
            for (int j = 0; j < 4; ++j) acc[mi][ni][j] = 0.f;

    cp_async_wait0();
    __syncthreads();

    // ---------------- layer 2: out = H @ W2 ----------------
    mma_block(aB, bB, acc);

    // ---------------- epilogue 2: + b2, fp32 store ----------------
#pragma unroll
    for (int mi = 0; mi < 2; ++mi) {
        const int rA = wm * 32 + mi * 16 + g;
        const int rB = rA + 8;
#pragma unroll
        for (int ni = 0; ni < 8; ++ni) {
            const int c = wn * 64 + ni * 8 + tg * 2;
            float2 bv = *reinterpret_cast<const float2*>(b2 + c);
            *reinterpret_cast<float2*>(out + (size_t)(e0 + rA) * DIM + c) =
                make_float2(acc[mi][ni][0] + bv.x, acc[mi][ni][1] + bv.y);
            *reinterpret_cast<float2*>(out + (size_t)(e0 + rB) * DIM + c) =
                make_float2(acc[mi][ni][2] + bv.x, acc[mi][ni][3] + bv.y);
        }
    }
}

extern "C" void kernel_launch(void* const* d_in, const int* in_sizes, int n_in,
                              void* d_out, int out_size) {
    const float* src  = (const float*)d_in[0];
    const float* dst  = (const float*)d_in[1];
    const float* edge = (const float*)d_in[2];
    const float* u    = (const float*)d_in[3];
    const int*   bat  = (const int*)d_in[4];
    const float* W1   = (const float*)d_in[5];
    const float* b1   = (const float*)d_in[6];
    const float* W2   = (const float*)d_in[7];
    const float* b2   = (const float*)d_in[8];
    float* out = (float*)d_out;
    (void)in_sizes; (void)n_in; (void)out_size;

    cudaFuncSetAttribute(edge_mlp_kernel,
                         cudaFuncAttributeMaxDynamicSharedMemorySize, SMEM_BYTES);

    prep_kernel<<<PREP_BLKS, 256>>>(bat, u, W1, b1, W2);
    edge_mlp_kernel<<<E_TOTAL / BM, NTHREADS, SMEM_BYTES>>>(src, dst, edge, b2, out);
}